// round 14
// baseline (speedup 1.0000x reference)
#include <cuda_runtime.h>
#include <cuda_bf16.h>

#define JAX_PARTITIONABLE 1

// ---------------- scratch (__device__ globals; no allocation) ----------------
__device__ float g_T[8192 * 128];          // X_in @ theta
__device__ float g_U[8192 * 128];          // xi @ w_trans0
__device__ float g_U1[8192 * 128];         // xi @ w_trans1
__device__ float g_X[8192 * 128];          // X1 then X2
__device__ float g_msg[4096 * 128];        // edge messages (ew-scaled)
__device__ float g_msgP[8 * 4096 * 128];   // split-K partials for Hs GEMM
__device__ float g_ZP[4 * 8192 * 128];     // split-K partials for Ht^T GEMM

// ------------------------------- helpers ------------------------------------
__device__ __forceinline__ unsigned rotl32(unsigned v, int s) {
    return __funnelshift_l(v, v, s);
}
__device__ __forceinline__ unsigned smem_u32(const void* p) {
    unsigned a;
    asm("{ .reg .u64 t; cvta.to.shared.u64 t, %1; cvt.u32.u64 %0, t; }"
        : "=r"(a) : "l"(p));
    return a;
}
__device__ __forceinline__ void cpa16(unsigned saddr, const float* g) {
    asm volatile("cp.async.cg.shared.global [%0], [%1], 16;"
                 :: "r"(saddr), "l"(g));
}
__device__ __forceinline__ void cpa_commit() {
    asm volatile("cp.async.commit_group;");
}
template <int N>
__device__ __forceinline__ void cpa_wait() {
    asm volatile("cp.async.wait_group %0;" :: "n"(N));
}

// bf16 2-way split of a k-pair (f0 = even k, f1 = odd k) -> packed hi, lo u32.
__device__ __forceinline__ void split_pair(float f0, float f1,
                                           unsigned& H, unsigned& L) {
    __nv_bfloat162 h = __floats2bfloat162_rn(f0, f1);
    float r0 = f0 - __bfloat162float(h.x);
    float r1 = f1 - __bfloat162float(h.y);
    __nv_bfloat162 l = __floats2bfloat162_rn(r0, r1);
    H = *reinterpret_cast<unsigned*>(&h);
    L = *reinterpret_cast<unsigned*>(&l);
}

// m16n8k16 bf16 mma, fp32 accumulate
__device__ __forceinline__ void mma16(float c[4], const unsigned a[4], const unsigned b[2]) {
    asm("mma.sync.aligned.m16n8k16.row.col.f32.bf16.bf16.f32 "
        "{%0,%1,%2,%3},{%4,%5,%6,%7},{%8,%9},{%0,%1,%2,%3};"
        : "+f"(c[0]), "+f"(c[1]), "+f"(c[2]), "+f"(c[3])
        : "r"(a[0]), "r"(a[1]), "r"(a[2]), "r"(a[3]), "r"(b[0]), "r"(b[1]));
}

// JAX threefry2x32, key = (0, 42). Random bits for flat element j of (8192,128).
__device__ __forceinline__ unsigned jax_dropout_bits(unsigned j) {
    const unsigned k0 = 0u, k1 = 42u;
    const unsigned ks2 = k0 ^ k1 ^ 0x1BD11BDAu;
    unsigned x0, x1;
#if JAX_PARTITIONABLE
    x0 = 0u + k0;
    x1 = j + k1;
#else
    const unsigned HALF = 524288u;
    unsigned i = (j < HALF) ? j : (j - HALF);
    x0 = i + k0;
    x1 = (i + HALF) + k1;
#endif
#define TFR(r) do { x0 += x1; x1 = rotl32(x1, (r)); x1 ^= x0; } while (0)
    TFR(13); TFR(15); TFR(26); TFR(6);   x0 += k1;  x1 += ks2 + 1u;
    TFR(17); TFR(29); TFR(16); TFR(24);  x0 += ks2; x1 += k0 + 2u;
    TFR(13); TFR(15); TFR(26); TFR(6);   x0 += k0;  x1 += k1 + 3u;
    TFR(17); TFR(29); TFR(16); TFR(24);  x0 += k1;  x1 += ks2 + 4u;
    TFR(13); TFR(15); TFR(26); TFR(6);   x0 += ks2; x1 += k0 + 5u;
#undef TFR
#if JAX_PARTITIONABLE
    return x0 ^ x1;
#else
    return (j < 524288u) ? x0 : x1;
#endif
}

// ============ 3-term bf16-split GEMM, cp.async staged, k64/iter ==============
// C[M,128] = op(A) @ B;  B is [K,128] row-major fp32.
//   TRANS_A=false: A [M,K] row-major (row stride lda)
//   TRANS_A=true : A [K,M] row-major (row stride lda), used as A^T
// 512 threads = 16 warps (4M x 4N), warp tile 32x32, k64/iter.
// Pipeline: cp.async f32 tiles into double-buffered raw stages (no registers),
// smem->smem bf16 hi/lo conversion at the barrier, mma on split buffers.
//
// SMEM map (u32 indices):
//   AsH[128][36] 4608 | AsL 4608 | BsH[32][136] 4352 | BsL 4352   (split bufs)
//   stage0: SA (128x68 or 64x132 f32 = 8704 max) + SB (64x132 = 8448)
//   stage1: same
static const int AH_O = 0, AL_O = 4608, BH_O = 9216, BL_O = 13568;
static const int STG_O = 17920;
static const int SA_SZ = 8704, SB_SZ = 8448;
static const int STG_STRIDE = SA_SZ + SB_SZ;          // 17152
static const int SM_BYTES = (STG_O + 2 * STG_STRIDE) * 4;   // 208896 B

template <bool TRANS_A>
__device__ __forceinline__ void issue_stage(
    const float* __restrict__ A, const float* __restrict__ B,
    int lda, int m0, int kc, unsigned sbase, int stg, int tid)
{
    const unsigned sa = sbase + (unsigned)(STG_O + stg * STG_STRIDE) * 4;
    const unsigned sb = sa + (unsigned)SA_SZ * 4;
#pragma unroll
    for (int i = 0; i < 4; ++i) {                     // A: 2048 16B chunks
        int c = tid + i * 512;
        if (TRANS_A) {
            int row = c >> 5, col = c & 31;           // 64 k-rows x 512B
            cpa16(sa + (unsigned)(row * 132 + col * 4) * 4,
                  A + (size_t)(kc + row) * lda + m0 + col * 4);
        } else {
            int row = c >> 4, col = c & 15;           // 128 m-rows x 256B
            cpa16(sa + (unsigned)(row * 68 + col * 4) * 4,
                  A + (size_t)(m0 + row) * lda + kc + col * 4);
        }
    }
#pragma unroll
    for (int i = 0; i < 4; ++i) {                     // B: 2048 16B chunks
        int c = tid + i * 512;
        int row = c >> 5, col = c & 31;               // 64 k-rows x 512B
        cpa16(sb + (unsigned)(row * 132 + col * 4) * 4,
              B + (size_t)(kc + row) * 128 + col * 4);
    }
    cpa_commit();
}

template <bool TRANS_A>
__device__ __forceinline__ void convert_stage(unsigned* __restrict__ sm,
                                              int stg, int tid)
{
    const float* SA = (const float*)(sm + STG_O + stg * STG_STRIDE);
    const float* SB = SA + SA_SZ;
    unsigned* AsH = sm + AH_O;
    unsigned* AsL = sm + AL_O;
    unsigned* BsH = sm + BH_O;
    unsigned* BsL = sm + BL_O;

    // ---- A: task = (m 0..127, kq8 0..3): 8 k-pairs (16 k's) for one row ----
    {
        const int m = tid & 127;
        const int kq8 = tid >> 7;                     // 0..3
        float v[16];
        if (TRANS_A) {
#pragma unroll
            for (int j = 0; j < 16; ++j)
                v[j] = SA[(kq8 * 16 + j) * 132 + m];
        } else {
#pragma unroll
            for (int j = 0; j < 16; ++j)
                v[j] = SA[m * 68 + kq8 * 16 + j];
        }
        unsigned H[8], L[8];
#pragma unroll
        for (int j = 0; j < 8; ++j)
            split_pair(v[2 * j], v[2 * j + 1], H[j], L[j]);
        const int o = m * 36 + kq8 * 8;
        *(uint4*)&AsH[o]     = make_uint4(H[0], H[1], H[2], H[3]);
        *(uint4*)&AsH[o + 4] = make_uint4(H[4], H[5], H[6], H[7]);
        *(uint4*)&AsL[o]     = make_uint4(L[0], L[1], L[2], L[3]);
        *(uint4*)&AsL[o + 4] = make_uint4(L[4], L[5], L[6], L[7]);
    }

    // ---- B: task = (p 0..31, nq 0..15): pair rows 2p,2p+1 for 8 n's -------
    {
        const int p = tid >> 4;                       // 0..31
        const int n0 = (tid & 15) * 8;
        float4 r0a = *(const float4*)&SB[(2 * p) * 132 + n0];
        float4 r0b = *(const float4*)&SB[(2 * p) * 132 + n0 + 4];
        float4 r1a = *(const float4*)&SB[(2 * p + 1) * 132 + n0];
        float4 r1b = *(const float4*)&SB[(2 * p + 1) * 132 + n0 + 4];
        unsigned H[8], L[8];
        split_pair(r0a.x, r1a.x, H[0], L[0]);
        split_pair(r0a.y, r1a.y, H[1], L[1]);
        split_pair(r0a.z, r1a.z, H[2], L[2]);
        split_pair(r0a.w, r1a.w, H[3], L[3]);
        split_pair(r0b.x, r1b.x, H[4], L[4]);
        split_pair(r0b.y, r1b.y, H[5], L[5]);
        split_pair(r0b.z, r1b.z, H[6], L[6]);
        split_pair(r0b.w, r1b.w, H[7], L[7]);
        const int o = p * 136 + n0;
        *(uint4*)&BsH[o]     = make_uint4(H[0], H[1], H[2], H[3]);
        *(uint4*)&BsH[o + 4] = make_uint4(H[4], H[5], H[6], H[7]);
        *(uint4*)&BsL[o]     = make_uint4(L[0], L[1], L[2], L[3]);
        *(uint4*)&BsL[o + 4] = make_uint4(L[4], L[5], L[6], L[7]);
    }
}

template <bool TRANS_A>
__device__ __forceinline__ void gemm_body(
    const float* __restrict__ A, const float* __restrict__ B,
    float* __restrict__ Cp, int lda, int k_iters, int mblk, int split, int gx)
{
    extern __shared__ __align__(16) unsigned sm[];
    const unsigned sbase = smem_u32(sm);
    const int tid = threadIdx.x;
    const int lane = tid & 31;
    const int wid = tid >> 5;              // 0..15
    const int wm = (wid & 3) * 32;
    const int wn = (wid >> 2) * 32;
    const int g = lane >> 2;               // 0..7
    const int t = lane & 3;                // 0..3
    const int m0 = mblk * 128;
    const int k00 = split * k_iters * 64;

    float acc[2][4][4];
#pragma unroll
    for (int mt = 0; mt < 2; ++mt)
#pragma unroll
        for (int nt = 0; nt < 4; ++nt)
#pragma unroll
            for (int i = 0; i < 4; ++i) acc[mt][nt][i] = 0.f;

    // prologue: async-fill stage 0
    issue_stage<TRANS_A>(A, B, lda, m0, k00, sbase, 0, tid);

    for (int it = 0; it < k_iters; ++it) {
        const bool hn = (it + 1 < k_iters);
        if (hn)   // async-fill next stage; overlaps with this iter's mmas
            issue_stage<TRANS_A>(A, B, lda, m0, k00 + (it + 1) * 64,
                                 sbase, (it + 1) & 1, tid);
        if (hn) cpa_wait<1>(); else cpa_wait<0>();   // stage `it` complete
        __syncthreads();                              // + prior compute done
        convert_stage<TRANS_A>(sm, it & 1, tid);
        __syncthreads();

        const unsigned* cAH = sm + AH_O;
        const unsigned* cAL = sm + AL_O;
        const unsigned* cBH = sm + BH_O;
        const unsigned* cBL = sm + BL_O;
#pragma unroll
        for (int ks = 0; ks < 4; ++ks) {              // four k16 sub-steps
            const int pb = ks * 8;
            unsigned aH[2][4], aL[2][4];
#pragma unroll
            for (int mt = 0; mt < 2; ++mt) {
                const int r0 = (wm + mt * 16 + g) * 36;
                const int r1 = r0 + 8 * 36;
                aH[mt][0] = cAH[r0 + pb + t];
                aH[mt][1] = cAH[r1 + pb + t];
                aH[mt][2] = cAH[r0 + pb + t + 4];
                aH[mt][3] = cAH[r1 + pb + t + 4];
                aL[mt][0] = cAL[r0 + pb + t];
                aL[mt][1] = cAL[r1 + pb + t];
                aL[mt][2] = cAL[r0 + pb + t + 4];
                aL[mt][3] = cAL[r1 + pb + t + 4];
            }
#pragma unroll
            for (int nt = 0; nt < 4; ++nt) {
                const int nb = wn + nt * 8 + g;
                const int j0 = (pb + t) * 136 + nb;
                const int j1 = (pb + t + 4) * 136 + nb;
                unsigned bH[2] = { cBH[j0], cBH[j1] };
                unsigned bL[2] = { cBL[j0], cBL[j1] };
#pragma unroll
                for (int mt = 0; mt < 2; ++mt) {
                    mma16(acc[mt][nt], aH[mt], bH);   // hi*hi
                    mma16(acc[mt][nt], aL[mt], bH);   // lo*hi
                    mma16(acc[mt][nt], aH[mt], bL);   // hi*lo
                }
            }
        }
    }

    float* Cb = Cp + (size_t)split * gx * (128 * 128) + (size_t)m0 * 128;
#pragma unroll
    for (int mt = 0; mt < 2; ++mt)
#pragma unroll
        for (int nt = 0; nt < 4; ++nt) {
            const int r = wm + mt * 16 + g;
            const int c = wn + nt * 8 + t * 2;
            *(float2*)&Cb[(size_t)r * 128 + c] =
                make_float2(acc[mt][nt][0], acc[mt][nt][1]);
            *(float2*)&Cb[(size_t)(r + 8) * 128 + c] =
                make_float2(acc[mt][nt][2], acc[mt][nt][3]);
        }
}

// ------------------------------ GEMM kernels ---------------------------------
template <bool TRANS_A>
__global__ __launch_bounds__(512, 1)
void gemm_big(const float* __restrict__ A, const float* __restrict__ B,
              float* __restrict__ Cp, int lda, int k_iters)
{
    gemm_body<TRANS_A>(A, B, Cp, lda, k_iters, blockIdx.x, blockIdx.y, gridDim.x);
}

struct GemmJob { const float* A; const float* B; float* C; };

__global__ __launch_bounds__(512, 1)
void gemm_small3(GemmJob j0, GemmJob j1, GemmJob j2)
{
    GemmJob j = (blockIdx.z == 0) ? j0 : ((blockIdx.z == 1) ? j1 : j2);
    gemm_body<false>(j.A, j.B, j.C, 128, 2, blockIdx.x, 0, 64);
}

__global__ __launch_bounds__(512, 1)
void gemm_small1(const float* __restrict__ A, const float* __restrict__ B,
                 float* __restrict__ C)
{
    gemm_body<false>(A, B, C, 128, 2, blockIdx.x, 0, 64);
}

// ------------------------ reduce / epilogue kernels --------------------------
__global__ void reduce_msg_k(const float* __restrict__ P, const float* __restrict__ ew,
                             float* __restrict__ out)
{
    const int i = blockIdx.x * 256 + threadIdx.x;
    float s = 0.f;
#pragma unroll
    for (int j = 0; j < 8; ++j) s += P[(size_t)j * (4096 * 128) + i];
    out[i] = s * ew[i >> 7];
}

__global__ void reduce_x1_k(const float* __restrict__ P, const float* __restrict__ U,
                            const float* __restrict__ bias, float* __restrict__ X1)
{
    const int i = blockIdx.x * 256 + threadIdx.x;
    float s = U[i] + bias[i & 127];
#pragma unroll
    for (int j = 0; j < 4; ++j) s += P[(size_t)j * (8192 * 128) + i];
    s = (s >= 0.f) ? s : 0.01f * s;
    const unsigned bits = jax_dropout_bits((unsigned)i);
    X1[i] = (bits & 0x80000000u) ? 0.f : (s + s);
}

__global__ void reduce_x2_k(const float* __restrict__ P, const float* __restrict__ U,
                            const float* __restrict__ bias, float* __restrict__ X2)
{
    const int i = blockIdx.x * 256 + threadIdx.x;
    float s = U[i] + bias[i & 127];
#pragma unroll
    for (int j = 0; j < 4; ++j) s += P[(size_t)j * (8192 * 128) + i];
    s = (s >= 0.f) ? s : 0.01f * s;
    s = (s >= 0.f) ? s : 0.01f * s;
    X2[i] = s;
}

__global__ void fc_k(const float* __restrict__ X, const float* __restrict__ state,
                     const float* __restrict__ fcw, const float* __restrict__ fcb,
                     float* __restrict__ out)
{
    const int n = blockIdx.x * 256 + threadIdx.x;
    const float4* xr = (const float4*)(X + (size_t)n * 128);
    const float4* w4 = (const float4*)fcw;
    float s = 0.f;
#pragma unroll
    for (int i = 0; i < 32; ++i) {
        float4 a = xr[i], b = w4[i];
        s += a.x * b.x + a.y * b.y + a.z * b.z + a.w * b.w;
    }
    out[n] = s + state[n] * fcw[128] + fcb[0];
}

// --------------------------------- launch ------------------------------------
extern "C" void kernel_launch(void* const* d_in, const int* in_sizes, int n_in,
                              void* d_out, int out_size)
{
    const float* xi   = (const float*)d_in[0];
    const float* x    = (const float*)d_in[1];
    const float* Ht   = (const float*)d_in[2];
    const float* Hs   = (const float*)d_in[3];
    const float* st   = (const float*)d_in[4];
    const float* w0   = (const float*)d_in[5];
    const float* th0  = (const float*)d_in[6];
    const float* ew0  = (const float*)d_in[7];
    const float* b0   = (const float*)d_in[8];
    const float* w1   = (const float*)d_in[9];
    const float* th1  = (const float*)d_in[10];
    const float* ew1  = (const float*)d_in[11];
    const float* b1   = (const float*)d_in[12];
    const float* fcw  = (const float*)d_in[13];
    const float* fcb  = (const float*)d_in[14];
    float* out = (float*)d_out;

    float *T, *U, *U1, *X, *M, *MP, *ZP;
    cudaGetSymbolAddress((void**)&T,  g_T);
    cudaGetSymbolAddress((void**)&U,  g_U);
    cudaGetSymbolAddress((void**)&U1, g_U1);
    cudaGetSymbolAddress((void**)&X,  g_X);
    cudaGetSymbolAddress((void**)&M,  g_msg);
    cudaGetSymbolAddress((void**)&MP, g_msgP);
    cudaGetSymbolAddress((void**)&ZP, g_ZP);

    cudaFuncSetAttribute(gemm_big<false>, cudaFuncAttributeMaxDynamicSharedMemorySize, SM_BYTES);
    cudaFuncSetAttribute(gemm_big<true>,  cudaFuncAttributeMaxDynamicSharedMemorySize, SM_BYTES);
    cudaFuncSetAttribute(gemm_small3,     cudaFuncAttributeMaxDynamicSharedMemorySize, SM_BYTES);
    cudaFuncSetAttribute(gemm_small1,     cudaFuncAttributeMaxDynamicSharedMemorySize, SM_BYTES);

    // independent small GEMMs: T = x@th0, U = xi@w0, U1 = xi@w1
    GemmJob j0 = { x,  th0, T  };
    GemmJob j1 = { xi, w0,  U  };
    GemmJob j2 = { xi, w1,  U1 };
    gemm_small3<<<dim3(64, 1, 3), 512, SM_BYTES>>>(j0, j1, j2);

    // ---- layer 0 ----
    gemm_big<false><<<dim3(32, 8), 512, SM_BYTES>>>(Hs, T, MP, 8192, 16);
    reduce_msg_k<<<2048, 256>>>(MP, ew0, M);
    gemm_big<true ><<<dim3(64, 4), 512, SM_BYTES>>>(Ht, M, ZP, 8192, 16);
    reduce_x1_k<<<4096, 256>>>(ZP, U, b0, X);

    // ---- layer 1 ----
    gemm_small1<<<64, 512, SM_BYTES>>>(X, th1, T);
    gemm_big<false><<<dim3(32, 8), 512, SM_BYTES>>>(Hs, T, MP, 8192, 16);
    reduce_msg_k<<<2048, 256>>>(MP, ew1, M);
    gemm_big<true ><<<dim3(64, 4), 512, SM_BYTES>>>(Ht, M, ZP, 8192, 16);
    reduce_x2_k<<<4096, 256>>>(ZP, U1, b1, X);

    // ---- head ----
    fc_k<<<32, 256>>>(X, st, fcw, fcb, out);
}

// round 15
// speedup vs baseline: 1.1867x; 1.1867x over previous
#include <cuda_runtime.h>
#include <cuda_bf16.h>

#define JAX_PARTITIONABLE 1

// ---------------- scratch (__device__ globals; no allocation) ----------------
__device__ float g_T[8192 * 128];          // X_in @ theta
__device__ float g_U[8192 * 128];          // xi @ w_trans0
__device__ float g_U1[8192 * 128];         // xi @ w_trans1
__device__ float g_msg[4096 * 128];        // edge messages (ew-scaled)
__device__ float g_msgP[4 * 4096 * 128];   // split-K partials for Hs GEMM (S=4)
__device__ float g_ZP[2 * 8192 * 128];     // split-K partials for Ht^T GEMM (S=2)

static const int ZP_STRIDE = 64 * 128 * 128;   // floats between Z partials

// ------------------------------- helpers ------------------------------------
__device__ __forceinline__ unsigned rotl32(unsigned v, int s) {
    return __funnelshift_l(v, v, s);
}

// bf16 2-way split of a k-pair (f0 = even k, f1 = odd k) -> packed hi, lo u32.
__device__ __forceinline__ void split_pair(float f0, float f1,
                                           unsigned& H, unsigned& L) {
    __nv_bfloat162 h = __floats2bfloat162_rn(f0, f1);
    float r0 = f0 - __bfloat162float(h.x);
    float r1 = f1 - __bfloat162float(h.y);
    __nv_bfloat162 l = __floats2bfloat162_rn(r0, r1);
    H = *reinterpret_cast<unsigned*>(&h);
    L = *reinterpret_cast<unsigned*>(&l);
}

// m16n8k16 bf16 mma, fp32 accumulate
__device__ __forceinline__ void mma16(float c[4], const unsigned a[4], const unsigned b[2]) {
    asm("mma.sync.aligned.m16n8k16.row.col.f32.bf16.bf16.f32 "
        "{%0,%1,%2,%3},{%4,%5,%6,%7},{%8,%9},{%0,%1,%2,%3};"
        : "+f"(c[0]), "+f"(c[1]), "+f"(c[2]), "+f"(c[3])
        : "r"(a[0]), "r"(a[1]), "r"(a[2]), "r"(a[3]), "r"(b[0]), "r"(b[1]));
}

// JAX threefry2x32, key = (0, 42). Random bits for flat element j of (8192,128).
__device__ __forceinline__ unsigned jax_dropout_bits(unsigned j) {
    const unsigned k0 = 0u, k1 = 42u;
    const unsigned ks2 = k0 ^ k1 ^ 0x1BD11BDAu;
    unsigned x0, x1;
#if JAX_PARTITIONABLE
    x0 = 0u + k0;
    x1 = j + k1;
#else
    const unsigned HALF = 524288u;
    unsigned i = (j < HALF) ? j : (j - HALF);
    x0 = i + k0;
    x1 = (i + HALF) + k1;
#endif
#define TFR(r) do { x0 += x1; x1 = rotl32(x1, (r)); x1 ^= x0; } while (0)
    TFR(13); TFR(15); TFR(26); TFR(6);   x0 += k1;  x1 += ks2 + 1u;
    TFR(17); TFR(29); TFR(16); TFR(24);  x0 += ks2; x1 += k0 + 2u;
    TFR(13); TFR(15); TFR(26); TFR(6);   x0 += k0;  x1 += k1 + 3u;
    TFR(17); TFR(29); TFR(16); TFR(24);  x0 += k1;  x1 += ks2 + 4u;
    TFR(13); TFR(15); TFR(26); TFR(6);   x0 += ks2; x1 += k0 + 5u;
#undef TFR
#if JAX_PARTITIONABLE
    return x0 ^ x1;
#else
    return (j < 524288u) ? x0 : x1;
#endif
}

// build one X1 float4 (fused reduce_x1: partials + U + bias, lrelu, dropout)
__device__ __forceinline__ float4 make_x1(const float* __restrict__ ZP,
                                          const float* __restrict__ U,
                                          const float* __restrict__ bias,
                                          int idx /*flat, mult of 4*/, int col)
{
    float4 u  = *(const float4*)(U + idx);
    float4 p0 = *(const float4*)(ZP + idx);
    float4 p1 = *(const float4*)(ZP + ZP_STRIDE + idx);
    float e[4] = { u.x + bias[col],     u.y + bias[col + 1],
                   u.z + bias[col + 2], u.w + bias[col + 3] };
    e[0] += p0.x; e[1] += p0.y; e[2] += p0.z; e[3] += p0.w;
    e[0] += p1.x; e[1] += p1.y; e[2] += p1.z; e[3] += p1.w;
    float4 r;
    float* rr = &r.x;
#pragma unroll
    for (int q = 0; q < 4; ++q) {
        float z = e[q];
        z = (z >= 0.f) ? z : 0.01f * z;                       // lrelu
        unsigned bits = jax_dropout_bits((unsigned)(idx + q));
        rr[q] = (bits & 0x80000000u) ? 0.f : (z + z);         // dropout p=.5
    }
    return r;
}

// ====================== 3-term bf16-split GEMM (k64/iter) ====================
// (identical inner loop to the 405.6us best kernel)
static const int ASZ = 4608, BSZ = 4352;
static const int BUF_STRIDE = 2 * ASZ + 2 * BSZ;   // 17920 u32
static const int SM_BYTES = BUF_STRIDE * 2 * 4;    // 143360 B

template <bool TRANS_A>
__device__ __forceinline__ float4 loadA(const float* __restrict__ A, int lda,
                                        int m0, int kc, int row, int kq) {
    if (TRANS_A) {
        const float* p = A + (size_t)(kc + kq * 4) * lda + m0 + row;
        float4 v;
        v.x = p[0];
        v.y = p[(size_t)lda];
        v.z = p[2 * (size_t)lda];
        v.w = p[3 * (size_t)lda];
        return v;
    } else {
        return *(const float4*)(A + (size_t)(m0 + row) * lda + kc + kq * 4);
    }
}

__device__ __forceinline__ void stA(unsigned* __restrict__ AsH,
                                    unsigned* __restrict__ AsL,
                                    int row, int kq, float4 v) {
    unsigned h0, l0, h1, l1;
    split_pair(v.x, v.y, h0, l0);
    split_pair(v.z, v.w, h1, l1);
    *(uint2*)&AsH[row * 36 + 2 * kq] = make_uint2(h0, h1);
    *(uint2*)&AsL[row * 36 + 2 * kq] = make_uint2(l0, l1);
}

__device__ __forceinline__ void stB(unsigned* __restrict__ BsH,
                                    unsigned* __restrict__ BsL,
                                    int p, int n, float4 r0, float4 r1) {
    unsigned h[4], l[4];
    split_pair(r0.x, r1.x, h[0], l[0]);
    split_pair(r0.y, r1.y, h[1], l[1]);
    split_pair(r0.z, r1.z, h[2], l[2]);
    split_pair(r0.w, r1.w, h[3], l[3]);
    *(uint4*)&BsH[p * 136 + n] = make_uint4(h[0], h[1], h[2], h[3]);
    *(uint4*)&BsL[p * 136 + n] = make_uint4(l[0], l[1], l[2], l[3]);
}

// A_SRC: 0 = plain global (loadA), 1 = fused X1 build (reduce+lrelu+dropout)
template <bool TRANS_A, int A_SRC>
__device__ __forceinline__ void gemm_body_bf(
    const float* __restrict__ A, const float* __restrict__ B,
    float* __restrict__ Cp, int lda, int k_iters, int mblk, int split, int gx,
    const float* __restrict__ xU, const float* __restrict__ xb)
{
    extern __shared__ unsigned sm[];
    const int tid = threadIdx.x;
    const int lane = tid & 31;
    const int wid = tid >> 5;              // 0..15
    const int wm = (wid & 3) * 32;
    const int wn = (wid >> 2) * 32;
    const int g = lane >> 2;               // 0..7
    const int t = lane & 3;                // 0..3
    const int m0 = mblk * 128;
    const int k00 = split * k_iters * 64;

    int ar_row[4], ar_kq[4];
#pragma unroll
    for (int r = 0; r < 4; ++r) {
        int task = tid + r * 512;
        if (TRANS_A) { ar_row[r] = task & 127; ar_kq[r] = task >> 7; }
        else         { ar_row[r] = task >> 4;  ar_kq[r] = task & 15; }
    }
    int b_p[2], b_n[2];
#pragma unroll
    for (int r = 0; r < 2; ++r) {
        int task = tid + r * 512;
        b_p[r] = task >> 5;
        b_n[r] = (task & 31) * 4;
    }

    float acc[2][4][4];
#pragma unroll
    for (int mt = 0; mt < 2; ++mt)
#pragma unroll
        for (int nt = 0; nt < 4; ++nt)
#pragma unroll
            for (int i = 0; i < 4; ++i) acc[mt][nt][i] = 0.f;

    float4 av[4], bv0[2], bv1[2];

    int kc = k00;
#pragma unroll
    for (int r = 0; r < 4; ++r) {
        if (A_SRC == 1)
            av[r] = make_x1(A, xU, xb,
                            (m0 + ar_row[r]) * 128 + kc + ar_kq[r] * 4,
                            kc + ar_kq[r] * 4);
        else
            av[r] = loadA<TRANS_A>(A, lda, m0, kc, ar_row[r], ar_kq[r]);
    }
#pragma unroll
    for (int r = 0; r < 2; ++r) {
        bv0[r] = *(const float4*)(B + (size_t)(kc + 2 * b_p[r]) * 128 + b_n[r]);
        bv1[r] = *(const float4*)(B + (size_t)(kc + 2 * b_p[r] + 1) * 128 + b_n[r]);
    }
#pragma unroll
    for (int r = 0; r < 4; ++r) stA(sm, sm + ASZ, ar_row[r], ar_kq[r], av[r]);
#pragma unroll
    for (int r = 0; r < 2; ++r)
        stB(sm + 2 * ASZ, sm + 2 * ASZ + BSZ, b_p[r], b_n[r], bv0[r], bv1[r]);
    __syncthreads();

    for (int it = 0; it < k_iters; ++it) {
        const unsigned* cur = sm + (it & 1) * BUF_STRIDE;
        const unsigned* cAH = cur;
        const unsigned* cAL = cur + ASZ;
        const unsigned* cBH = cur + 2 * ASZ;
        const unsigned* cBL = cur + 2 * ASZ + BSZ;
        const bool hn = (it + 1 < k_iters);

        if (hn) {
            kc = k00 + (it + 1) * 64;
#pragma unroll
            for (int r = 0; r < 4; ++r) {
                if (A_SRC == 1)
                    av[r] = make_x1(A, xU, xb,
                                    (m0 + ar_row[r]) * 128 + kc + ar_kq[r] * 4,
                                    kc + ar_kq[r] * 4);
                else
                    av[r] = loadA<TRANS_A>(A, lda, m0, kc, ar_row[r], ar_kq[r]);
            }
#pragma unroll
            for (int r = 0; r < 2; ++r) {
                bv0[r] = *(const float4*)(B + (size_t)(kc + 2 * b_p[r]) * 128 + b_n[r]);
                bv1[r] = *(const float4*)(B + (size_t)(kc + 2 * b_p[r] + 1) * 128 + b_n[r]);
            }
        }

#pragma unroll
        for (int ks = 0; ks < 4; ++ks) {
            const int pb = ks * 8;
            unsigned aH[2][4], aL[2][4];
#pragma unroll
            for (int mt = 0; mt < 2; ++mt) {
                const int r0 = (wm + mt * 16 + g) * 36;
                const int r1 = r0 + 8 * 36;
                aH[mt][0] = cAH[r0 + pb + t];
                aH[mt][1] = cAH[r1 + pb + t];
                aH[mt][2] = cAH[r0 + pb + t + 4];
                aH[mt][3] = cAH[r1 + pb + t + 4];
                aL[mt][0] = cAL[r0 + pb + t];
                aL[mt][1] = cAL[r1 + pb + t];
                aL[mt][2] = cAL[r0 + pb + t + 4];
                aL[mt][3] = cAL[r1 + pb + t + 4];
            }
#pragma unroll
            for (int nt = 0; nt < 4; ++nt) {
                const int nb = wn + nt * 8 + g;
                const int j0 = (pb + t) * 136 + nb;
                const int j1 = (pb + t + 4) * 136 + nb;
                unsigned bH[2] = { cBH[j0], cBH[j1] };
                unsigned bL[2] = { cBL[j0], cBL[j1] };
#pragma unroll
                for (int mt = 0; mt < 2; ++mt) {
                    mma16(acc[mt][nt], aH[mt], bH);
                    mma16(acc[mt][nt], aL[mt], bH);
                    mma16(acc[mt][nt], aH[mt], bL);
                }
            }
        }

        if (hn) {
            unsigned* nb = sm + ((it + 1) & 1) * BUF_STRIDE;
#pragma unroll
            for (int r = 0; r < 4; ++r)
                stA(nb, nb + ASZ, ar_row[r], ar_kq[r], av[r]);
#pragma unroll
            for (int r = 0; r < 2; ++r)
                stB(nb + 2 * ASZ, nb + 2 * ASZ + BSZ, b_p[r], b_n[r], bv0[r], bv1[r]);
        }
        __syncthreads();
    }

    float* Cb = Cp + (size_t)split * gx * (128 * 128) + (size_t)m0 * 128;
#pragma unroll
    for (int mt = 0; mt < 2; ++mt)
#pragma unroll
        for (int nt = 0; nt < 4; ++nt) {
            const int r = wm + mt * 16 + g;
            const int c = wn + nt * 8 + t * 2;
            *(float2*)&Cb[(size_t)r * 128 + c] =
                make_float2(acc[mt][nt][0], acc[mt][nt][1]);
            *(float2*)&Cb[(size_t)(r + 8) * 128 + c] =
                make_float2(acc[mt][nt][2], acc[mt][nt][3]);
        }
}

// ------------------------------ GEMM kernels ---------------------------------
template <bool TRANS_A>
__global__ __launch_bounds__(512, 1)
void gemm_big(const float* __restrict__ A, const float* __restrict__ B,
              float* __restrict__ Cp, int lda, int k_iters)
{
    gemm_body_bf<TRANS_A, 0>(A, B, Cp, lda, k_iters,
                             blockIdx.x, blockIdx.y, gridDim.x, nullptr, nullptr);
}

struct GemmJob { const float* A; const float* B; float* C; };

__global__ __launch_bounds__(512, 1)
void gemm_small3(GemmJob j0, GemmJob j1, GemmJob j2)
{
    GemmJob j = (blockIdx.z == 0) ? j0 : ((blockIdx.z == 1) ? j1 : j2);
    gemm_body_bf<false, 0>(j.A, j.B, j.C, 128, 2, blockIdx.x, 0, 64,
                           nullptr, nullptr);
}

// layer-1 theta GEMM with fused X1 construction (A = lrelu/dropout(ZP+U+b0))
__global__ __launch_bounds__(512, 1)
void gemm_x1theta(const float* __restrict__ ZP, const float* __restrict__ th1,
                  float* __restrict__ T,
                  const float* __restrict__ U, const float* __restrict__ b0)
{
    gemm_body_bf<false, 1>(ZP, th1, T, 128, 2, blockIdx.x, 0, 64, U, b0);
}

// ------------------------ reduce / epilogue kernels --------------------------
__global__ void reduce_msg_k(const float* __restrict__ P, const float* __restrict__ ew,
                             float* __restrict__ out)
{
    const int i = blockIdx.x * 256 + threadIdx.x;
    float s = 0.f;
#pragma unroll
    for (int j = 0; j < 4; ++j) s += P[(size_t)j * (4096 * 128) + i];
    out[i] = s * ew[i >> 7];
}

// fc with fused reduce_x2 (X2 built on the fly from Z partials)
__global__ void fc_fused_k(const float* __restrict__ ZP, const float* __restrict__ U1,
                           const float* __restrict__ b1,
                           const float* __restrict__ state,
                           const float* __restrict__ fcw, const float* __restrict__ fcb,
                           float* __restrict__ out)
{
    const int n = blockIdx.x * 256 + threadIdx.x;
    const float4* u4  = (const float4*)(U1 + (size_t)n * 128);
    const float4* p04 = (const float4*)(ZP + (size_t)n * 128);
    const float4* p14 = (const float4*)(ZP + ZP_STRIDE + (size_t)n * 128);
    const float4* w4  = (const float4*)fcw;
    float s = 0.f;
#pragma unroll
    for (int i = 0; i < 32; ++i) {
        float4 u = u4[i], p0 = p04[i], p1 = p14[i], w = w4[i];
        float e[4] = { u.x + b1[4 * i],     u.y + b1[4 * i + 1],
                       u.z + b1[4 * i + 2], u.w + b1[4 * i + 3] };
        e[0] += p0.x; e[1] += p0.y; e[2] += p0.z; e[3] += p0.w;
        e[0] += p1.x; e[1] += p1.y; e[2] += p1.z; e[3] += p1.w;
        const float* ww = &w.x;
#pragma unroll
        for (int q = 0; q < 4; ++q) {
            float z = e[q];
            z = (z >= 0.f) ? z : 0.01f * z;   // conv lrelu
            z = (z >= 0.f) ? z : 0.01f * z;   // forward lrelu
            s += z * ww[q];
        }
    }
    out[n] = s + state[n] * fcw[128] + fcb[0];
}

// --------------------------------- launch ------------------------------------
extern "C" void kernel_launch(void* const* d_in, const int* in_sizes, int n_in,
                              void* d_out, int out_size)
{
    const float* xi   = (const float*)d_in[0];
    const float* x    = (const float*)d_in[1];
    const float* Ht   = (const float*)d_in[2];
    const float* Hs   = (const float*)d_in[3];
    const float* st   = (const float*)d_in[4];
    const float* w0   = (const float*)d_in[5];
    const float* th0  = (const float*)d_in[6];
    const float* ew0  = (const float*)d_in[7];
    const float* b0   = (const float*)d_in[8];
    const float* w1   = (const float*)d_in[9];
    const float* th1  = (const float*)d_in[10];
    const float* ew1  = (const float*)d_in[11];
    const float* b1   = (const float*)d_in[12];
    const float* fcw  = (const float*)d_in[13];
    const float* fcb  = (const float*)d_in[14];
    float* out = (float*)d_out;

    float *T, *U, *U1, *M, *MP, *ZP;
    cudaGetSymbolAddress((void**)&T,  g_T);
    cudaGetSymbolAddress((void**)&U,  g_U);
    cudaGetSymbolAddress((void**)&U1, g_U1);
    cudaGetSymbolAddress((void**)&M,  g_msg);
    cudaGetSymbolAddress((void**)&MP, g_msgP);
    cudaGetSymbolAddress((void**)&ZP, g_ZP);

    cudaFuncSetAttribute(gemm_big<false>, cudaFuncAttributeMaxDynamicSharedMemorySize, SM_BYTES);
    cudaFuncSetAttribute(gemm_big<true>,  cudaFuncAttributeMaxDynamicSharedMemorySize, SM_BYTES);
    cudaFuncSetAttribute(gemm_small3,     cudaFuncAttributeMaxDynamicSharedMemorySize, SM_BYTES);
    cudaFuncSetAttribute(gemm_x1theta,    cudaFuncAttributeMaxDynamicSharedMemorySize, SM_BYTES);

    // independent small GEMMs: T = x@th0, U = xi@w0, U1 = xi@w1
    GemmJob j0 = { x,  th0, T  };
    GemmJob j1 = { xi, w0,  U  };
    GemmJob j2 = { xi, w1,  U1 };
    gemm_small3<<<dim3(64, 1, 3), 512, SM_BYTES>>>(j0, j1, j2);

    // ---- layer 0 ----  (single-wave grids: 32x4 = 128, 64x2 = 128 CTAs)
    gemm_big<false><<<dim3(32, 4), 512, SM_BYTES>>>(Hs, T, MP, 8192, 32);
    reduce_msg_k<<<2048, 256>>>(MP, ew0, M);
    gemm_big<true ><<<dim3(64, 2), 512, SM_BYTES>>>(Ht, M, ZP, 8192, 32);

    // ---- layer 1 ----  (X1 built inside the theta GEMM's staging)
    gemm_x1theta<<<64, 512, SM_BYTES>>>(ZP, th1, T, U, b0);
    gemm_big<false><<<dim3(32, 4), 512, SM_BYTES>>>(Hs, T, MP, 8192, 32);
    reduce_msg_k<<<2048, 256>>>(MP, ew1, M);
    gemm_big<true ><<<dim3(64, 2), 512, SM_BYTES>>>(Ht, M, ZP, 8192, 32);

    // ---- head ----  (X2 built inside fc)
    fc_fused_k<<<32, 256>>>(ZP, U1, b1, st, fcw, fcb, out);
}